// round 1
// baseline (speedup 1.0000x reference)
#include <cuda_runtime.h>
#include <cuda_bf16.h>
#include <math.h>

// Problem constants (static per reference).
#define NN   50000
#define EE   800000
#define FEA  256
#define HID  256
#define CLS  64
#define THETA 0.5f

// ---------------- device scratch (no allocs allowed) ----------------
__device__ int    g_deg[NN];
__device__ float  g_dinv[NN];
__device__ float  g_h  [(size_t)NN * HID];   // h = x @ W (current layer)
__device__ float  g_acc[(size_t)NN * HID];   // scatter accumulator
__device__ float  g_x1 [(size_t)NN * HID];   // relu'd conv1 output
__device__ double g_pos_loss;
__device__ double g_neg_loss;
__device__ unsigned long long g_pos_cnt;
__device__ unsigned long long g_neg_cnt;

// ---------------- degree + dinv ----------------
__global__ void k_deg_count(const int* __restrict__ row, int e) {
    int i = blockIdx.x * blockDim.x + threadIdx.x;
    if (i < e) atomicAdd(&g_deg[row[i]], 1);
}

__global__ void k_dinv(int n) {
    int i = blockIdx.x * blockDim.x + threadIdx.x;
    if (i < n) {
        // self loop adds 1 to every node's degree -> always > 0
        g_dinv[i] = rsqrtf((float)(g_deg[i] + 1));
    }
}

// ---------------- simple 64x64 tiled fp32 GEMM ----------------
// C[M,Nc] = A[M,K] @ B[K,Nc] (+ bias). K, Nc multiples of 64 here (K=256).
__global__ void k_gemm64(const float* __restrict__ A, const float* __restrict__ B,
                         float* __restrict__ C, const float* __restrict__ bias,
                         int M, int K, int Nc) {
    __shared__ float As[16][65];
    __shared__ float Bs[16][65];
    const int bm = blockIdx.y * 64;
    const int bn = blockIdx.x * 64;
    const int tx = threadIdx.x;    // 0..15
    const int ty = threadIdx.y;    // 0..15
    const int tid = ty * 16 + tx;

    float c[4][4];
#pragma unroll
    for (int i = 0; i < 4; i++)
#pragma unroll
        for (int j = 0; j < 4; j++) c[i][j] = 0.f;

    for (int k0 = 0; k0 < K; k0 += 16) {
#pragma unroll
        for (int l = 0; l < 4; l++) {
            int idx = tid + l * 256;          // 0..1023
            // A tile: 64 rows x 16 k  (k fast -> 64B segments)
            int ka = idx & 15, ma = idx >> 4;
            int gm = bm + ma;
            As[ka][ma] = (gm < M) ? A[(size_t)gm * K + k0 + ka] : 0.f;
            // B tile: 16 k x 64 n (n fast -> coalesced)
            int nb = idx & 63, kb = idx >> 6;
            Bs[kb][nb] = B[(size_t)(k0 + kb) * Nc + bn + nb];
        }
        __syncthreads();
#pragma unroll
        for (int k = 0; k < 16; k++) {
            float a[4], b[4];
#pragma unroll
            for (int i = 0; i < 4; i++) a[i] = As[k][ty * 4 + i];
#pragma unroll
            for (int j = 0; j < 4; j++) b[j] = Bs[k][tx * 4 + j];
#pragma unroll
            for (int i = 0; i < 4; i++)
#pragma unroll
                for (int j = 0; j < 4; j++) c[i][j] = fmaf(a[i], b[j], c[i][j]);
        }
        __syncthreads();
    }
#pragma unroll
    for (int i = 0; i < 4; i++) {
        int gm = bm + ty * 4 + i;
        if (gm >= M) continue;
#pragma unroll
        for (int j = 0; j < 4; j++) {
            int gn = bn + tx * 4 + j;
            float v = c[i][j];
            if (bias) v += bias[gn];
            C[(size_t)gm * Nc + gn] = v;
        }
    }
}

// ---------------- edge scatter: acc[row] += dinv[row]*dinv[col]*h[col] ----------------
// one warp per edge, 256 features via 2x float4 per lane
__global__ void k_scatter(const int* __restrict__ row, const int* __restrict__ col,
                          const float* __restrict__ h, float* __restrict__ acc, int e) {
    int gw = (blockIdx.x * blockDim.x + threadIdx.x) >> 5;
    int lane = threadIdx.x & 31;
    if (gw >= e) return;
    int r = row[gw];
    int c = col[gw];
    float nrm = g_dinv[r] * g_dinv[c];
    const float4* hc = (const float4*)(h + (size_t)c * HID);
    float* orow = acc + (size_t)r * HID;
#pragma unroll
    for (int j = 0; j < 2; j++) {
        int q = lane + 32 * j;        // float4 index 0..63
        float4 v = hc[q];
        int base = q * 4;
        atomicAdd(orow + base + 0, nrm * v.x);
        atomicAdd(orow + base + 1, nrm * v.y);
        atomicAdd(orow + base + 2, nrm * v.z);
        atomicAdd(orow + base + 3, nrm * v.w);
    }
}

// ---------------- finalize conv1: x1 = relu(acc + dinv^2*h + b1) ----------------
__global__ void k_finalize_relu(const float* __restrict__ acc, const float* __restrict__ h,
                                const float* __restrict__ b, float* __restrict__ out) {
    size_t i = (size_t)blockIdx.x * blockDim.x + threadIdx.x;
    if (i >= (size_t)NN * HID) return;
    int r = (int)(i >> 8);          // /256
    int f = (int)(i & 255);
    float di = g_dinv[r];
    float v = acc[i] + di * di * h[i] + b[f];
    out[i] = fmaxf(v, 0.f);
}

// ---------------- finalize conv2 + double l2norm -> rep ----------------
__global__ void k_finalize_norm(const float* __restrict__ acc, const float* __restrict__ h,
                                const float* __restrict__ b, float* __restrict__ rep) {
    int r = blockIdx.x;
    int f = threadIdx.x;            // 256 threads
    float di = g_dinv[r];
    size_t i = (size_t)r * HID + f;
    float v = acc[i] + di * di * h[i] + b[f];

    // block reduce sum of squares
    float s = v * v;
#pragma unroll
    for (int o = 16; o; o >>= 1) s += __shfl_xor_sync(0xffffffffu, s, o);
    __shared__ float ws[8];
    __shared__ float total;
    int wid = threadIdx.x >> 5;
    if ((threadIdx.x & 31) == 0) ws[wid] = s;
    __syncthreads();
    if (threadIdx.x == 0) {
        float t = 0.f;
#pragma unroll
        for (int k = 0; k < 8; k++) t += ws[k];
        total = t;
    }
    __syncthreads();
    float s1 = sqrtf(total);
    float d1 = fmaxf(s1, 1e-12f);
    float u  = v / d1;
    float s2 = s1 / d1;               // norm of u
    float d2 = fmaxf(s2, 1e-12f);
    rep[i] = u / d2;
}

// ---------------- loss ----------------
__device__ __forceinline__ float dot256(const float* __restrict__ a,
                                        const float* __restrict__ b, int lane) {
    const float4* a4 = (const float4*)a;
    const float4* b4 = (const float4*)b;
    float s = 0.f;
#pragma unroll
    for (int j = 0; j < 2; j++) {
        float4 x = a4[lane + 32 * j];
        float4 y = b4[lane + 32 * j];
        s += x.x * y.x + x.y * y.y + x.z * y.z + x.w * y.w;
    }
#pragma unroll
    for (int o = 16; o; o >>= 1) s += __shfl_xor_sync(0xffffffffu, s, o);
    return s;
}

__global__ void k_zero_loss() {
    g_pos_loss = 0.0; g_neg_loss = 0.0; g_pos_cnt = 0ull; g_neg_cnt = 0ull;
}

// one warp per (pos or neg) edge; 512 threads = 16 warps per block
__global__ void k_loss(const int* __restrict__ e0, const int* __restrict__ e1,
                       const int* __restrict__ n0, const int* __restrict__ n1,
                       const float* __restrict__ feat, const float* __restrict__ rep,
                       const float* __restrict__ ls) {
    int gw = (blockIdx.x * blockDim.x + threadIdx.x) >> 5;
    int lane = threadIdx.x & 31;
    int wid = threadIdx.x >> 5;

    float pos_local = 0.f, neg_local = 0.f;
    int pc = 0, nc = 0;
    if (gw < EE) {
        int a = e0[gw], b = e1[gw];
        if (a < b) {
            float fsim = dot256(feat + (size_t)a * FEA, feat + (size_t)b * FEA, lane);
            float wv   = dot256(rep  + (size_t)a * HID, rep  + (size_t)b * HID, lane);
            float pos = fsim * THETA + fmaxf(wv, 0.f) * (1.0f - THETA);
            float t = pos - ls[gw];
            pos_local = t * t;
            pc = 1;
        }
    } else if (gw < 2 * EE) {
        int k = gw - EE;
        int a = n0[k], b = n1[k];
        if (a < b) {
            float wv = fmaxf(dot256(rep + (size_t)a * HID, rep + (size_t)b * HID, lane), 0.f);
            neg_local = wv * wv;
            nc = 1;
        }
    }

    __shared__ float sp[16], sn[16];
    __shared__ int   cp[16], cn[16];
    if (lane == 0) { sp[wid] = pos_local; sn[wid] = neg_local; cp[wid] = pc; cn[wid] = nc; }
    __syncthreads();
    if (threadIdx.x == 0) {
        double p = 0.0, q = 0.0; int c1 = 0, c2 = 0;
#pragma unroll
        for (int k = 0; k < 16; k++) { p += sp[k]; q += sn[k]; c1 += cp[k]; c2 += cn[k]; }
        if (p != 0.0) atomicAdd(&g_pos_loss, p);
        if (q != 0.0) atomicAdd(&g_neg_loss, q);
        if (c1) atomicAdd(&g_pos_cnt, (unsigned long long)c1);
        if (c2) atomicAdd(&g_neg_cnt, (unsigned long long)c2);
    }
}

__global__ void k_finish_loss(float* __restrict__ out_scalar) {
    double tot = g_pos_loss + g_neg_loss;
    double denom = (double)(g_pos_cnt + g_neg_cnt);
    out_scalar[0] = (float)(tot * (double)NN / denom);
}

// ---------------- launch ----------------
extern "C" void kernel_launch(void* const* d_in, const int* in_sizes, int n_in,
                              void* d_out, int out_size) {
    const int*   edge_index = (const int*)d_in[0];       // [2,E]
    const float* features   = (const float*)d_in[1];     // [N,256]
    const float* label_sm   = (const float*)d_in[2];     // [E]
    const int*   neg_edge   = (const int*)d_in[3];       // [2,E]
    const float* W1 = (const float*)d_in[4];
    const float* b1 = (const float*)d_in[5];
    const float* W2 = (const float*)d_in[6];
    const float* b2 = (const float*)d_in[7];
    const float* Wy = (const float*)d_in[8];
    const float* by = (const float*)d_in[9];

    const int* e0 = edge_index;
    const int* e1 = edge_index + EE;
    const int* n0 = neg_edge;
    const int* n1 = neg_edge + EE;

    float* rep_out  = (float*)d_out;                           // [N,256]
    float* loss_out = (float*)d_out + (size_t)NN * HID;        // [1]
    float* y_out    = loss_out + 1;                            // [N,64]

    // resolve scratch addresses (host-side queries, graph-capture safe)
    void *p_deg, *p_acc;
    cudaGetSymbolAddress(&p_deg, g_deg);
    cudaGetSymbolAddress(&p_acc, g_acc);
    float* acc = (float*)p_acc;
    float* h   = nullptr;
    {
        void* ph; cudaGetSymbolAddress(&ph, g_h); h = (float*)ph;
    }
    float* x1 = nullptr;
    {
        void* px; cudaGetSymbolAddress(&px, g_x1); x1 = (float*)px;
    }

    const size_t accBytes = (size_t)NN * HID * sizeof(float);

    // 1. degrees
    cudaMemsetAsync(p_deg, 0, NN * sizeof(int));
    k_deg_count<<<(EE + 255) / 256, 256>>>(e0, EE);
    k_dinv<<<(NN + 255) / 256, 256>>>(NN);

    // 2. conv1: h = features @ W1 ; scatter ; x1 = relu(acc + dinv^2 h + b1)
    {
        dim3 grid(HID / 64, (NN + 63) / 64), block(16, 16);
        k_gemm64<<<grid, block>>>(features, W1, h, nullptr, NN, FEA, HID);
    }
    cudaMemsetAsync(p_acc, 0, accBytes);
    k_scatter<<<(EE * 32 + 255) / 256, 256>>>(e0, e1, h, acc, EE);
    k_finalize_relu<<<(int)(((size_t)NN * HID + 255) / 256), 256>>>(acc, h, b1, x1);

    // 3. conv2: h = x1 @ W2 ; scatter ; rep = l2norm(l2norm(acc + dinv^2 h + b2))
    {
        dim3 grid(HID / 64, (NN + 63) / 64), block(16, 16);
        k_gemm64<<<grid, block>>>(x1, W2, h, nullptr, NN, HID, HID);
    }
    cudaMemsetAsync(p_acc, 0, accBytes);
    k_scatter<<<(EE * 32 + 255) / 256, 256>>>(e0, e1, h, acc, EE);
    k_finalize_norm<<<NN, 256>>>(acc, h, b2, rep_out);

    // 4. y = rep @ Wy + by
    {
        dim3 grid(CLS / 64, (NN + 63) / 64), block(16, 16);
        k_gemm64<<<grid, block>>>(rep_out, Wy, y_out, by, NN, HID, CLS);
    }

    // 5. loss
    k_zero_loss<<<1, 1>>>();
    {
        long long warps = 2LL * EE;
        int blocks = (int)((warps * 32 + 511) / 512);
        k_loss<<<blocks, 512>>>(e0, e1, n0, n1, features, rep_out, label_sm);
    }
    k_finish_loss<<<1, 1>>>(loss_out);
}

// round 3
// speedup vs baseline: 1.4787x; 1.4787x over previous
#include <cuda_runtime.h>
#include <cuda_bf16.h>
#include <math.h>

// Problem constants (static per reference).
#define NN   50000
#define EE   800000
#define FEA  256
#define HID  256
#define CLS  64
#define THETA 0.5f

// ---------------- device scratch (no allocs allowed) ----------------
__device__ int    g_deg[NN];
__device__ float  g_dinv[NN];
__device__ int    g_rowptr[NN + 1];
__device__ int    g_cursor[NN];
__device__ int    g_ecol[EE];                // CSR column indices
__device__ float  g_h  [(size_t)NN * HID];   // h = x @ W (current layer)
__device__ float  g_x1 [(size_t)NN * HID];   // relu'd conv1 output
__device__ double g_pos_loss;
__device__ double g_neg_loss;
__device__ unsigned long long g_pos_cnt;
__device__ unsigned long long g_neg_cnt;

// ---------------- degree ----------------
__global__ void k_deg_count(const int* __restrict__ row, int e) {
    int i = blockIdx.x * blockDim.x + threadIdx.x;
    if (i < e) atomicAdd(&g_deg[row[i]], 1);
}

// ---------------- single-block scan over g_deg -> g_rowptr, g_cursor, g_dinv ----------------
__global__ void k_scan(int n) {
    const int T = 1024;
    const int C = (NN + T - 1) / T;          // 49
    __shared__ int part[T];
    int t = threadIdx.x;
    int base = t * C;
    int local = 0;
#pragma unroll 4
    for (int j = 0; j < C; j++) {
        int idx = base + j;
        if (idx < n) local += g_deg[idx];
    }
    part[t] = local;
    __syncthreads();
    for (int off = 1; off < T; off <<= 1) {
        int v = (t >= off) ? part[t - off] : 0;
        __syncthreads();
        part[t] += v;
        __syncthreads();
    }
    int run = (t == 0) ? 0 : part[t - 1];    // exclusive prefix for this chunk
    for (int j = 0; j < C; j++) {
        int idx = base + j;
        if (idx < n) {
            g_rowptr[idx] = run;
            g_cursor[idx] = run;
            int d = g_deg[idx];
            run += d;
            g_dinv[idx] = rsqrtf((float)(d + 1));   // +1 self loop
        }
    }
    if (t == T - 1) g_rowptr[n] = EE;
}

// ---------------- CSR fill ----------------
__global__ void k_csr_fill(const int* __restrict__ row, const int* __restrict__ col, int e) {
    int i = blockIdx.x * blockDim.x + threadIdx.x;
    if (i >= e) return;
    int r = row[i];
    int p = atomicAdd(&g_cursor[r], 1);
    g_ecol[p] = col[i];
}

// ---------------- simple 64x64 tiled fp32 GEMM ----------------
__global__ void k_gemm64(const float* __restrict__ A, const float* __restrict__ B,
                         float* __restrict__ C, const float* __restrict__ bias,
                         int M, int K, int Nc) {
    __shared__ float As[16][65];
    __shared__ float Bs[16][65];
    const int bm = blockIdx.y * 64;
    const int bn = blockIdx.x * 64;
    const int tx = threadIdx.x;
    const int ty = threadIdx.y;
    const int tid = ty * 16 + tx;

    float c[4][4];
#pragma unroll
    for (int i = 0; i < 4; i++)
#pragma unroll
        for (int j = 0; j < 4; j++) c[i][j] = 0.f;

    for (int k0 = 0; k0 < K; k0 += 16) {
#pragma unroll
        for (int l = 0; l < 4; l++) {
            int idx = tid + l * 256;
            int ka = idx & 15, ma = idx >> 4;
            int gm = bm + ma;
            As[ka][ma] = (gm < M) ? A[(size_t)gm * K + k0 + ka] : 0.f;
            int nb = idx & 63, kb = idx >> 6;
            Bs[kb][nb] = B[(size_t)(k0 + kb) * Nc + bn + nb];
        }
        __syncthreads();
#pragma unroll
        for (int k = 0; k < 16; k++) {
            float a[4], b[4];
#pragma unroll
            for (int i = 0; i < 4; i++) a[i] = As[k][ty * 4 + i];
#pragma unroll
            for (int j = 0; j < 4; j++) b[j] = Bs[k][tx * 4 + j];
#pragma unroll
            for (int i = 0; i < 4; i++)
#pragma unroll
                for (int j = 0; j < 4; j++) c[i][j] = fmaf(a[i], b[j], c[i][j]);
        }
        __syncthreads();
    }
#pragma unroll
    for (int i = 0; i < 4; i++) {
        int gm = bm + ty * 4 + i;
        if (gm >= M) continue;
#pragma unroll
        for (int j = 0; j < 4; j++) {
            int gn = bn + tx * 4 + j;
            float v = c[i][j];
            if (bias) v += bias[gn];
            C[(size_t)gm * Nc + gn] = v;
        }
    }
}

// ---------------- fused gather conv (no atomics) ----------------
// out_row = dinv[r]*( sum_edges dinv[c]*h[c] + dinv[r]*h[r] ) + b
// MODE 0: relu -> out ; MODE 1: double-l2norm -> out
template <int MODE>
__global__ void __launch_bounds__(256) k_gather(const float* __restrict__ h,
                                                const float* __restrict__ bias,
                                                float* __restrict__ out) {
    const int r = blockIdx.x;
    const int f = threadIdx.x;            // one thread per feature
    const int s = g_rowptr[r];
    const int e = g_rowptr[r + 1];

    __shared__ int   sc[256];
    __shared__ float sd[256];

    float acc0 = 0.f, acc1 = 0.f, acc2 = 0.f, acc3 = 0.f;
    for (int base = s; base < e; base += 256) {
        int nb = min(256, e - base);
        if (f < nb) {
            int c = g_ecol[base + f];
            sc[f] = c;
            sd[f] = g_dinv[c];
        }
        __syncthreads();
        int j = 0;
        for (; j + 3 < nb; j += 4) {
            int c0 = sc[j], c1 = sc[j + 1], c2 = sc[j + 2], c3 = sc[j + 3];
            float v0 = __ldg(h + (size_t)c0 * HID + f);
            float v1 = __ldg(h + (size_t)c1 * HID + f);
            float v2 = __ldg(h + (size_t)c2 * HID + f);
            float v3 = __ldg(h + (size_t)c3 * HID + f);
            acc0 = fmaf(sd[j],     v0, acc0);
            acc1 = fmaf(sd[j + 1], v1, acc1);
            acc2 = fmaf(sd[j + 2], v2, acc2);
            acc3 = fmaf(sd[j + 3], v3, acc3);
        }
        for (; j < nb; j++) {
            acc0 = fmaf(sd[j], __ldg(h + (size_t)sc[j] * HID + f), acc0);
        }
        __syncthreads();
    }
    const float di = g_dinv[r];
    float hv = h[(size_t)r * HID + f];
    float v = di * ((acc0 + acc1) + (acc2 + acc3) + di * hv) + bias[f];

    if (MODE == 0) {
        out[(size_t)r * HID + f] = fmaxf(v, 0.f);
    } else {
        float sq = v * v;
#pragma unroll
        for (int o = 16; o; o >>= 1) sq += __shfl_xor_sync(0xffffffffu, sq, o);
        __shared__ float ws[8];
        __shared__ float total;
        int wid = threadIdx.x >> 5;
        if ((threadIdx.x & 31) == 0) ws[wid] = sq;
        __syncthreads();
        if (threadIdx.x == 0) {
            float t = 0.f;
#pragma unroll
            for (int k = 0; k < 8; k++) t += ws[k];
            total = t;
        }
        __syncthreads();
        float s1 = sqrtf(total);
        float d1 = fmaxf(s1, 1e-12f);
        float u  = v / d1;
        float s2 = s1 / d1;
        float d2 = fmaxf(s2, 1e-12f);
        out[(size_t)r * HID + f] = u / d2;
    }
}

// ---------------- loss ----------------
__device__ __forceinline__ float dot256(const float* __restrict__ a,
                                        const float* __restrict__ b, int lane) {
    const float4* a4 = (const float4*)a;
    const float4* b4 = (const float4*)b;
    float s = 0.f;
#pragma unroll
    for (int j = 0; j < 2; j++) {
        float4 x = a4[lane + 32 * j];
        float4 y = b4[lane + 32 * j];
        s += x.x * y.x + x.y * y.y + x.z * y.z + x.w * y.w;
    }
#pragma unroll
    for (int o = 16; o; o >>= 1) s += __shfl_xor_sync(0xffffffffu, s, o);
    return s;
}

__global__ void k_zero_loss() {
    g_pos_loss = 0.0; g_neg_loss = 0.0; g_pos_cnt = 0ull; g_neg_cnt = 0ull;
}

__global__ void k_loss(const int* __restrict__ e0, const int* __restrict__ e1,
                       const int* __restrict__ n0, const int* __restrict__ n1,
                       const float* __restrict__ feat, const float* __restrict__ rep,
                       const float* __restrict__ ls) {
    int gw = (blockIdx.x * blockDim.x + threadIdx.x) >> 5;
    int lane = threadIdx.x & 31;
    int wid = threadIdx.x >> 5;

    float pos_local = 0.f, neg_local = 0.f;
    int pc = 0, nc = 0;
    if (gw < EE) {
        int a = e0[gw], b = e1[gw];
        if (a < b) {
            float fsim = dot256(feat + (size_t)a * FEA, feat + (size_t)b * FEA, lane);
            float wv   = dot256(rep  + (size_t)a * HID, rep  + (size_t)b * HID, lane);
            float pos = fsim * THETA + fmaxf(wv, 0.f) * (1.0f - THETA);
            float t = pos - ls[gw];
            pos_local = t * t;
            pc = 1;
        }
    } else if (gw < 2 * EE) {
        int k = gw - EE;
        int a = n0[k], b = n1[k];
        if (a < b) {
            float wv = fmaxf(dot256(rep + (size_t)a * HID, rep + (size_t)b * HID, lane), 0.f);
            neg_local = wv * wv;
            nc = 1;
        }
    }

    __shared__ float sp[16], sn[16];
    __shared__ int   cp[16], cn[16];
    if (lane == 0) { sp[wid] = pos_local; sn[wid] = neg_local; cp[wid] = pc; cn[wid] = nc; }
    __syncthreads();
    if (threadIdx.x == 0) {
        double p = 0.0, q = 0.0; int c1 = 0, c2 = 0;
#pragma unroll
        for (int k = 0; k < 16; k++) { p += sp[k]; q += sn[k]; c1 += cp[k]; c2 += cn[k]; }
        if (p != 0.0) atomicAdd(&g_pos_loss, p);
        if (q != 0.0) atomicAdd(&g_neg_loss, q);
        if (c1) atomicAdd(&g_pos_cnt, (unsigned long long)c1);
        if (c2) atomicAdd(&g_neg_cnt, (unsigned long long)c2);
    }
}

__global__ void k_finish_loss(float* __restrict__ out_scalar) {
    double tot = g_pos_loss + g_neg_loss;
    double denom = (double)(g_pos_cnt + g_neg_cnt);
    out_scalar[0] = (float)(tot * (double)NN / denom);
}

// ---------------- launch ----------------
extern "C" void kernel_launch(void* const* d_in, const int* in_sizes, int n_in,
                              void* d_out, int out_size) {
    const int*   edge_index = (const int*)d_in[0];       // [2,E]
    const float* features   = (const float*)d_in[1];     // [N,256]
    const float* label_sm   = (const float*)d_in[2];     // [E]
    const int*   neg_edge   = (const int*)d_in[3];       // [2,E]
    const float* W1 = (const float*)d_in[4];
    const float* b1 = (const float*)d_in[5];
    const float* W2 = (const float*)d_in[6];
    const float* b2 = (const float*)d_in[7];
    const float* Wy = (const float*)d_in[8];
    const float* by = (const float*)d_in[9];

    const int* e0 = edge_index;
    const int* e1 = edge_index + EE;
    const int* n0 = neg_edge;
    const int* n1 = neg_edge + EE;

    float* rep_out  = (float*)d_out;                           // [N,256]
    float* loss_out = (float*)d_out + (size_t)NN * HID;        // [1]
    float* y_out    = loss_out + 1;                            // [N,64]

    void *p_deg, *ph, *px;
    cudaGetSymbolAddress(&p_deg, g_deg);
    cudaGetSymbolAddress(&ph, g_h);
    cudaGetSymbolAddress(&px, g_x1);
    float* h  = (float*)ph;
    float* x1 = (float*)px;

    // 1. CSR build (degree -> scan -> fill). Also computes dinv.
    cudaMemsetAsync(p_deg, 0, NN * sizeof(int));
    k_deg_count<<<(EE + 255) / 256, 256>>>(e0, EE);
    k_scan<<<1, 1024>>>(NN);
    k_csr_fill<<<(EE + 255) / 256, 256>>>(e0, e1, EE);

    // 2. conv1: h = features @ W1 ; fused gather+relu -> x1
    {
        dim3 grid(HID / 64, (NN + 63) / 64), block(16, 16);
        k_gemm64<<<grid, block>>>(features, W1, h, nullptr, NN, FEA, HID);
    }
    k_gather<0><<<NN, 256>>>(h, b1, x1);

    // 3. conv2: h = x1 @ W2 ; fused gather + double l2norm -> rep
    {
        dim3 grid(HID / 64, (NN + 63) / 64), block(16, 16);
        k_gemm64<<<grid, block>>>(x1, W2, h, nullptr, NN, HID, HID);
    }
    k_gather<1><<<NN, 256>>>(h, b2, rep_out);

    // 4. y = rep @ Wy + by
    {
        dim3 grid(CLS / 64, (NN + 63) / 64), block(16, 16);
        k_gemm64<<<grid, block>>>(rep_out, Wy, y_out, by, NN, HID, CLS);
    }

    // 5. loss
    k_zero_loss<<<1, 1>>>();
    {
        long long warps = 2LL * EE;
        int blocks = (int)((warps * 32 + 511) / 512);
        k_loss<<<blocks, 512>>>(e0, e1, n0, n1, features, rep_out, label_sm);
    }
    k_finish_loss<<<1, 1>>>(loss_out);
}

// round 5
// speedup vs baseline: 1.6360x; 1.1063x over previous
#include <cuda_runtime.h>
#include <cuda_bf16.h>
#include <math.h>

// Problem constants (static per reference).
#define NN   50000
#define EE   800000
#define FEA  256
#define HID  256
#define CLS  64
#define THETA 0.5f

// ---------------- device scratch (no allocs allowed) ----------------
__device__ int    g_deg[NN];
__device__ float  g_dinv[NN];
__device__ int    g_rowptr[NN + 1];
__device__ int    g_cursor[NN];
__device__ int    g_ecol[EE];                // CSR column indices
__device__ float  g_h  [(size_t)NN * HID];   // h = x @ W (current layer)
__device__ float  g_x1 [(size_t)NN * HID];   // relu'd conv1 output
__device__ double g_pos_loss;
__device__ double g_neg_loss;
__device__ unsigned long long g_pos_cnt;
__device__ unsigned long long g_neg_cnt;

// ---------------- degree ----------------
__global__ void k_deg_count(const int* __restrict__ row, int e) {
    int i = blockIdx.x * blockDim.x + threadIdx.x;
    if (i < e) atomicAdd(&g_deg[row[i]], 1);
}

// ---------------- single-block scan over g_deg -> g_rowptr, g_cursor, g_dinv ----------------
__global__ void k_scan(int n) {
    const int T = 1024;
    const int C = (NN + T - 1) / T;          // 49
    __shared__ int part[T];
    int t = threadIdx.x;
    int base = t * C;
    int local = 0;
#pragma unroll 4
    for (int j = 0; j < C; j++) {
        int idx = base + j;
        if (idx < n) local += g_deg[idx];
    }
    part[t] = local;
    __syncthreads();
    for (int off = 1; off < T; off <<= 1) {
        int v = (t >= off) ? part[t - off] : 0;
        __syncthreads();
        part[t] += v;
        __syncthreads();
    }
    int run = (t == 0) ? 0 : part[t - 1];
    for (int j = 0; j < C; j++) {
        int idx = base + j;
        if (idx < n) {
            g_rowptr[idx] = run;
            g_cursor[idx] = run;
            int d = g_deg[idx];
            run += d;
            g_dinv[idx] = rsqrtf((float)(d + 1));   // +1 self loop
        }
    }
    if (t == T - 1) g_rowptr[n] = EE;
}

// ---------------- CSR fill ----------------
__global__ void k_csr_fill(const int* __restrict__ row, const int* __restrict__ col, int e) {
    int i = blockIdx.x * blockDim.x + threadIdx.x;
    if (i >= e) return;
    int r = row[i];
    int p = atomicAdd(&g_cursor[r], 1);
    g_ecol[p] = col[i];
}

// ---------------- 128x(TN) register-blocked SGEMM ----------------
// 256 threads, micro-tile 8 x (TN/16), BK=8. K multiple of 8, Nc multiple of TN.
// V4STORE=false for outputs that are only 4B-aligned.
template <int TN, bool V4STORE>
__global__ void __launch_bounds__(256) k_gemm128(const float* __restrict__ A,
                                                 const float* __restrict__ B,
                                                 float* __restrict__ C,
                                                 const float* __restrict__ bias,
                                                 int M, int K, int Nc) {
    constexpr int CN = TN / 16;               // cols per thread (8 or 4)
    __shared__ float As[8][128];              // [k][m]
    __shared__ float Bs[8][TN];               // [k][n]

    const int bm = blockIdx.y * 128;
    const int bn = blockIdx.x * TN;
    const int tid = threadIdx.x;
    const int tx = tid & 15;                  // n-dir
    const int ty = tid >> 4;                  // m-dir

    const int a_row = tid >> 1;               // 0..127
    const int a_kq  = (tid & 1) * 4;          // 0 or 4

    float acc[8][CN];
#pragma unroll
    for (int i = 0; i < 8; i++)
#pragma unroll
        for (int j = 0; j < CN; j++) acc[i][j] = 0.f;

    const int m_frag = ty * 8;
    const int n_frag = tx * CN;

    for (int k0 = 0; k0 < K; k0 += 8) {
        {
            int gm = bm + a_row;
            float4 v = make_float4(0.f, 0.f, 0.f, 0.f);
            if (gm < M) v = *(const float4*)(A + (size_t)gm * K + k0 + a_kq);
            As[a_kq + 0][a_row] = v.x;
            As[a_kq + 1][a_row] = v.y;
            As[a_kq + 2][a_row] = v.z;
            As[a_kq + 3][a_row] = v.w;
        }
        if (TN == 128) {
            int krow = tid >> 5, c4 = (tid & 31) * 4;
            float4 v = *(const float4*)(B + (size_t)(k0 + krow) * Nc + bn + c4);
            *(float4*)(&Bs[krow][c4]) = v;
        } else {
            if (tid < 128) {
                int krow = tid >> 4, c4 = (tid & 15) * 4;
                float4 v = *(const float4*)(B + (size_t)(k0 + krow) * Nc + bn + c4);
                *(float4*)(&Bs[krow][c4]) = v;
            }
        }
        __syncthreads();

#pragma unroll
        for (int k = 0; k < 8; k++) {
            float a[8], b[CN];
            *(float4*)(a)     = *(const float4*)(&As[k][m_frag]);
            *(float4*)(a + 4) = *(const float4*)(&As[k][m_frag + 4]);
            *(float4*)(b)     = *(const float4*)(&Bs[k][n_frag]);
            if (CN == 8) *(float4*)(b + 4) = *(const float4*)(&Bs[k][n_frag + 4]);
#pragma unroll
            for (int i = 0; i < 8; i++)
#pragma unroll
                for (int j = 0; j < CN; j++) acc[i][j] = fmaf(a[i], b[j], acc[i][j]);
        }
        __syncthreads();
    }

#pragma unroll
    for (int i = 0; i < 8; i++) {
        int gm = bm + m_frag + i;
        if (gm >= M) continue;
        float* crow = C + (size_t)gm * Nc + bn + n_frag;
        if (V4STORE) {
#pragma unroll
            for (int j = 0; j < CN; j += 4) {
                float4 v;
                v.x = acc[i][j + 0]; v.y = acc[i][j + 1];
                v.z = acc[i][j + 2]; v.w = acc[i][j + 3];
                if (bias) {
                    v.x += bias[bn + n_frag + j + 0];
                    v.y += bias[bn + n_frag + j + 1];
                    v.z += bias[bn + n_frag + j + 2];
                    v.w += bias[bn + n_frag + j + 3];
                }
                *(float4*)(crow + j) = v;
            }
        } else {
#pragma unroll
            for (int j = 0; j < CN; j++) {
                float v = acc[i][j];
                if (bias) v += bias[bn + n_frag + j];
                crow[j] = v;
            }
        }
    }
}

// ---------------- fused gather conv (no atomics) ----------------
// out_row = dinv[r]*( sum_edges dinv[c]*h[c] + dinv[r]*h[r] ) + b
// MODE 0: relu -> out ; MODE 1: double-l2norm -> out
template <int MODE>
__global__ void __launch_bounds__(256) k_gather(const float* __restrict__ h,
                                                const float* __restrict__ bias,
                                                float* __restrict__ out) {
    const int r = blockIdx.x;
    const int f = threadIdx.x;
    const int s = g_rowptr[r];
    const int e = g_rowptr[r + 1];

    __shared__ int   sc[256];
    __shared__ float sd[256];

    float acc0 = 0.f, acc1 = 0.f, acc2 = 0.f, acc3 = 0.f;
    for (int base = s; base < e; base += 256) {
        int nb = min(256, e - base);
        if (f < nb) {
            int c = g_ecol[base + f];
            sc[f] = c;
            sd[f] = g_dinv[c];
        }
        __syncthreads();
        int j = 0;
        for (; j + 3 < nb; j += 4) {
            int c0 = sc[j], c1 = sc[j + 1], c2 = sc[j + 2], c3 = sc[j + 3];
            float v0 = __ldg(h + (size_t)c0 * HID + f);
            float v1 = __ldg(h + (size_t)c1 * HID + f);
            float v2 = __ldg(h + (size_t)c2 * HID + f);
            float v3 = __ldg(h + (size_t)c3 * HID + f);
            acc0 = fmaf(sd[j],     v0, acc0);
            acc1 = fmaf(sd[j + 1], v1, acc1);
            acc2 = fmaf(sd[j + 2], v2, acc2);
            acc3 = fmaf(sd[j + 3], v3, acc3);
        }
        for (; j < nb; j++) {
            acc0 = fmaf(sd[j], __ldg(h + (size_t)sc[j] * HID + f), acc0);
        }
        __syncthreads();
    }
    const float di = g_dinv[r];
    float hv = h[(size_t)r * HID + f];
    float v = di * ((acc0 + acc1) + (acc2 + acc3) + di * hv) + bias[f];

    if (MODE == 0) {
        out[(size_t)r * HID + f] = fmaxf(v, 0.f);
    } else {
        float sq = v * v;
#pragma unroll
        for (int o = 16; o; o >>= 1) sq += __shfl_xor_sync(0xffffffffu, sq, o);
        __shared__ float ws[8];
        __shared__ float total;
        int wid = threadIdx.x >> 5;
        if ((threadIdx.x & 31) == 0) ws[wid] = sq;
        __syncthreads();
        if (threadIdx.x == 0) {
            float t = 0.f;
#pragma unroll
            for (int k = 0; k < 8; k++) t += ws[k];
            total = t;
        }
        __syncthreads();
        float s1 = sqrtf(total);
        float d1 = fmaxf(s1, 1e-12f);
        float u  = v / d1;
        float s2 = s1 / d1;
        float d2 = fmaxf(s2, 1e-12f);
        out[(size_t)r * HID + f] = u / d2;
    }
}

// ---------------- loss ----------------
__device__ __forceinline__ float dot256(const float* __restrict__ a,
                                        const float* __restrict__ b, int lane) {
    const float4* a4 = (const float4*)a;
    const float4* b4 = (const float4*)b;
    float s = 0.f;
#pragma unroll
    for (int j = 0; j < 2; j++) {
        float4 x = a4[lane + 32 * j];
        float4 y = b4[lane + 32 * j];
        s += x.x * y.x + x.y * y.y + x.z * y.z + x.w * y.w;
    }
#pragma unroll
    for (int o = 16; o; o >>= 1) s += __shfl_xor_sync(0xffffffffu, s, o);
    return s;
}

__global__ void k_zero_loss() {
    g_pos_loss = 0.0; g_neg_loss = 0.0; g_pos_cnt = 0ull; g_neg_cnt = 0ull;
}

__global__ void k_loss(const int* __restrict__ e0, const int* __restrict__ e1,
                       const int* __restrict__ n0, const int* __restrict__ n1,
                       const float* __restrict__ feat, const float* __restrict__ rep,
                       const float* __restrict__ ls) {
    int gw = (blockIdx.x * blockDim.x + threadIdx.x) >> 5;
    int lane = threadIdx.x & 31;
    int wid = threadIdx.x >> 5;

    float pos_local = 0.f, neg_local = 0.f;
    int pc = 0, nc = 0;
    if (gw < EE) {
        int a = e0[gw], b = e1[gw];
        if (a < b) {
            float fsim = dot256(feat + (size_t)a * FEA, feat + (size_t)b * FEA, lane);
            float wv   = dot256(rep  + (size_t)a * HID, rep  + (size_t)b * HID, lane);
            float pos = fsim * THETA + fmaxf(wv, 0.f) * (1.0f - THETA);
            float t = pos - ls[gw];
            pos_local = t * t;
            pc = 1;
        }
    } else if (gw < 2 * EE) {
        int k = gw - EE;
        int a = n0[k], b = n1[k];
        if (a < b) {
            float wv = fmaxf(dot256(rep + (size_t)a * HID, rep + (size_t)b * HID, lane), 0.f);
            neg_local = wv * wv;
            nc = 1;
        }
    }

    __shared__ float sp[16], sn[16];
    __shared__ int   cp[16], cn[16];
    if (lane == 0) { sp[wid] = pos_local; sn[wid] = neg_local; cp[wid] = pc; cn[wid] = nc; }
    __syncthreads();
    if (threadIdx.x == 0) {
        double p = 0.0, q = 0.0; int c1 = 0, c2 = 0;
#pragma unroll
        for (int k = 0; k < 16; k++) { p += sp[k]; q += sn[k]; c1 += cp[k]; c2 += cn[k]; }
        if (p != 0.0) atomicAdd(&g_pos_loss, p);
        if (q != 0.0) atomicAdd(&g_neg_loss, q);
        if (c1) atomicAdd(&g_pos_cnt, (unsigned long long)c1);
        if (c2) atomicAdd(&g_neg_cnt, (unsigned long long)c2);
    }
}

__global__ void k_finish_loss(float* __restrict__ out_scalar) {
    double tot = g_pos_loss + g_neg_loss;
    double denom = (double)(g_pos_cnt + g_neg_cnt);
    out_scalar[0] = (float)(tot * (double)NN / denom);
}

// ---------------- launch ----------------
extern "C" void kernel_launch(void* const* d_in, const int* in_sizes, int n_in,
                              void* d_out, int out_size) {
    const int*   edge_index = (const int*)d_in[0];       // [2,E]
    const float* features   = (const float*)d_in[1];     // [N,256]
    const float* label_sm   = (const float*)d_in[2];     // [E]
    const int*   neg_edge   = (const int*)d_in[3];       // [2,E]
    const float* W1 = (const float*)d_in[4];
    const float* b1 = (const float*)d_in[5];
    const float* W2 = (const float*)d_in[6];
    const float* b2 = (const float*)d_in[7];
    const float* Wy = (const float*)d_in[8];
    const float* by = (const float*)d_in[9];

    const int* e0 = edge_index;
    const int* e1 = edge_index + EE;
    const int* n0 = neg_edge;
    const int* n1 = neg_edge + EE;

    float* rep_out  = (float*)d_out;                           // [N,256]
    float* loss_out = (float*)d_out + (size_t)NN * HID;        // [1]
    float* y_out    = loss_out + 1;                            // [N,64] -- only 4B aligned!

    void *p_deg, *ph, *px;
    cudaGetSymbolAddress(&p_deg, g_deg);
    cudaGetSymbolAddress(&ph, g_h);
    cudaGetSymbolAddress(&px, g_x1);
    float* h  = (float*)ph;
    float* x1 = (float*)px;

    // 1. CSR build (degree -> scan -> fill). Also computes dinv.
    cudaMemsetAsync(p_deg, 0, NN * sizeof(int));
    k_deg_count<<<(EE + 255) / 256, 256>>>(e0, EE);
    k_scan<<<1, 1024>>>(NN);
    k_csr_fill<<<(EE + 255) / 256, 256>>>(e0, e1, EE);

    // 2. conv1: h = features @ W1 ; fused gather+relu -> x1
    {
        dim3 grid(HID / 128, (NN + 127) / 128), block(256);
        k_gemm128<128, true><<<grid, block>>>(features, W1, h, nullptr, NN, FEA, HID);
    }
    k_gather<0><<<NN, 256>>>(h, b1, x1);

    // 3. conv2: h = x1 @ W2 ; fused gather + double l2norm -> rep
    {
        dim3 grid(HID / 128, (NN + 127) / 128), block(256);
        k_gemm128<128, true><<<grid, block>>>(x1, W2, h, nullptr, NN, HID, HID);
    }
    k_gather<1><<<NN, 256>>>(h, b2, rep_out);

    // 4. y = rep @ Wy + by  (y_out is 4B-aligned only -> scalar stores)
    {
        dim3 grid(CLS / 64, (NN + 127) / 128), block(256);
        k_gemm128<64, false><<<grid, block>>>(rep_out, Wy, y_out, by, NN, HID, CLS);
    }

    // 5. loss
    k_zero_loss<<<1, 1>>>();
    {
        long long warps = 2LL * EE;
        int blocks = (int)((warps * 32 + 511) / 512);
        k_loss<<<blocks, 512>>>(e0, e1, n0, n1, features, rep_out, label_sm);
    }
    k_finish_loss<<<1, 1>>>(loss_out);
}